// round 1
// baseline (speedup 1.0000x reference)
#include <cuda_runtime.h>
#include <math.h>

#define EMB   256
#define NEGO  8192
#define NSIDE 8192
#define TOPK  16

// Scratch (device globals: allocation-free contract)
__device__ float g_q[(size_t)NEGO * EMB];
__device__ float g_k[(size_t)NSIDE * EMB];
__device__ float g_v[(size_t)NSIDE * EMB];
__device__ float g_S[(size_t)NEGO * NSIDE];

// C[m][n] = (sum_d A'[m][d] * B[n][d] + bias[n]) * scale
// A' = A (elementwise * Amul if HAS_MUL). A,B row-major with row stride EMB.
// Tiles: BM=BN=128, BK=16. 256 threads, 8x8 accumulators per thread.
template <bool HAS_MUL, bool HAS_BIAS>
__global__ __launch_bounds__(256, 2) void sgemm_nt(
    const float* __restrict__ A, const float* __restrict__ Amul,
    const float* __restrict__ B, const float* __restrict__ bias,
    float* __restrict__ C, int ldc, float scale)
{
    __shared__ float sA[16][132];   // [k][m], padded (132) to cut STS conflicts
    __shared__ float sB[16][132];   // [k][n]

    const int tid = threadIdx.x;
    const int tx  = tid & 15;       // n subtile
    const int ty  = tid >> 4;       // m subtile
    const int m0  = blockIdx.y * 128;
    const int n0  = blockIdx.x * 128;

    float acc[8][8];
#pragma unroll
    for (int i = 0; i < 8; i++)
#pragma unroll
        for (int j = 0; j < 8; j++) acc[i][j] = 0.f;

    for (int k0 = 0; k0 < EMB; k0 += 16) {
        // Load 128x16 A and B tiles (512 float4 chunks each -> 2 per thread)
#pragma unroll
        for (int h = 0; h < 2; h++) {
            const int c   = tid + h * 256;       // chunk id [0,512)
            const int r   = c >> 2;              // tile row [0,128)
            const int col = (c & 3) * 4;         // tile col {0,4,8,12}

            float4 av = *(const float4*)&A[(size_t)(m0 + r) * EMB + k0 + col];
            if (HAS_MUL) {
                float4 mv = *(const float4*)&Amul[(size_t)(m0 + r) * EMB + k0 + col];
                av.x *= mv.x; av.y *= mv.y; av.z *= mv.z; av.w *= mv.w;
            }
            sA[col + 0][r] = av.x;
            sA[col + 1][r] = av.y;
            sA[col + 2][r] = av.z;
            sA[col + 3][r] = av.w;

            float4 bv = *(const float4*)&B[(size_t)(n0 + r) * EMB + k0 + col];
            sB[col + 0][r] = bv.x;
            sB[col + 1][r] = bv.y;
            sB[col + 2][r] = bv.z;
            sB[col + 3][r] = bv.w;
        }
        __syncthreads();

#pragma unroll 2
        for (int kk = 0; kk < 16; kk++) {
            float a[8], b[8];
            *(float4*)&a[0] = *(const float4*)&sA[kk][ty * 8 + 0];
            *(float4*)&a[4] = *(const float4*)&sA[kk][ty * 8 + 4];
            *(float4*)&b[0] = *(const float4*)&sB[kk][tx * 8 + 0];
            *(float4*)&b[4] = *(const float4*)&sB[kk][tx * 8 + 4];
#pragma unroll
            for (int i = 0; i < 8; i++)
#pragma unroll
                for (int j = 0; j < 8; j++)
                    acc[i][j] = fmaf(a[i], b[j], acc[i][j]);
        }
        __syncthreads();
    }

    // Epilogue
    float bn[8];
#pragma unroll
    for (int j = 0; j < 8; j++) bn[j] = HAS_BIAS ? bias[n0 + tx * 8 + j] : 0.f;

#pragma unroll
    for (int i = 0; i < 8; i++) {
        float4 o0, o1;
        o0.x = (acc[i][0] + bn[0]) * scale;
        o0.y = (acc[i][1] + bn[1]) * scale;
        o0.z = (acc[i][2] + bn[2]) * scale;
        o0.w = (acc[i][3] + bn[3]) * scale;
        o1.x = (acc[i][4] + bn[4]) * scale;
        o1.y = (acc[i][5] + bn[5]) * scale;
        o1.z = (acc[i][6] + bn[6]) * scale;
        o1.w = (acc[i][7] + bn[7]) * scale;
        float* cp = &C[(size_t)(m0 + ty * 8 + i) * (size_t)ldc + n0 + tx * 8];
        *(float4*)(cp + 0) = o0;
        *(float4*)(cp + 4) = o1;
    }
}

// One warp per ego row: scan 8192 scores, keep top-16 (value,index), softmax,
// gather v rows, weighted sum into out[row][0..255].
__global__ __launch_bounds__(256) void topk_agg(
    const float* __restrict__ S, const float* __restrict__ V,
    float* __restrict__ out)
{
    const int warp = threadIdx.x >> 5;
    const int lane = threadIdx.x & 31;
    const int row  = blockIdx.x * 8 + warp;

    __shared__ float hv_s[8][16];
    __shared__ int   hi_s[8][16];
    float* hv = hv_s[warp];
    int*   hi = hi_s[warp];

    if (lane < 16) { hv[lane] = -INFINITY; hi[lane] = 0; }
    __syncwarp();

    float kth = -INFINITY;  // current 16th-best (min of heap), warp-uniform
    const float* Srow = S + (size_t)row * NSIDE;

    for (int j0 = 0; j0 < NSIDE; j0 += 32) {
        const float s = Srow[j0 + lane];
        unsigned m = __ballot_sync(0xffffffffu, s > kth);
        while (m) {
            const int src = __ffs(m) - 1;
            m &= m - 1;
            const float v = __shfl_sync(0xffffffffu, s, src);
            if (v > kth) {  // warp-uniform (v, kth uniform)
                float nk = 0.f;
                if (lane == 0) {
                    int am = 0; float mv = hv[0];
#pragma unroll
                    for (int t = 1; t < 16; t++)
                        if (hv[t] < mv) { mv = hv[t]; am = t; }
                    hv[am] = v; hi[am] = j0 + src;
                    mv = hv[0];
#pragma unroll
                    for (int t = 1; t < 16; t++) mv = fminf(mv, hv[t]);
                    nk = mv;
                }
                kth = __shfl_sync(0xffffffffu, nk, 0);
            }
        }
    }
    __syncwarp();

    // Softmax over the 16 kept scores (lanes 0..15 hold one each)
    float topv = (lane < 16) ? hv[lane] : -INFINITY;
    float mx = topv;
#pragma unroll
    for (int o = 16; o > 0; o >>= 1) mx = fmaxf(mx, __shfl_xor_sync(0xffffffffu, mx, o));
    float e = (lane < 16) ? expf(topv - mx) : 0.f;
    float sum = e;
#pragma unroll
    for (int o = 16; o > 0; o >>= 1) sum += __shfl_xor_sync(0xffffffffu, sum, o);
    if (lane < 16) hv[lane] = e / sum;
    __syncwarp();

    // Weighted gather-sum of v rows: lane covers dims [lane*8, lane*8+8)
    float4 a0 = {0.f, 0.f, 0.f, 0.f}, a1 = {0.f, 0.f, 0.f, 0.f};
#pragma unroll
    for (int t = 0; t < 16; t++) {
        const float wt = hv[t];
        const float4* vr = (const float4*)(V + (size_t)hi[t] * EMB) + lane * 2;
        const float4 x = vr[0];
        const float4 y = vr[1];
        a0.x = fmaf(wt, x.x, a0.x); a0.y = fmaf(wt, x.y, a0.y);
        a0.z = fmaf(wt, x.z, a0.z); a0.w = fmaf(wt, x.w, a0.w);
        a1.x = fmaf(wt, y.x, a1.x); a1.y = fmaf(wt, y.y, a1.y);
        a1.z = fmaf(wt, y.z, a1.z); a1.w = fmaf(wt, y.w, a1.w);
    }
    float4* op = (float4*)(out + (size_t)row * EMB) + lane * 2;
    op[0] = a0;
    op[1] = a1;
}

extern "C" void kernel_launch(void* const* d_in, const int* in_sizes, int n_in,
                              void* d_out, int out_size)
{
    const float* ego  = (const float*)d_in[0];
    const float* side = (const float*)d_in[1];
    const float* rel  = (const float*)d_in[2];
    const float* Wq   = (const float*)d_in[3];
    const float* bq   = (const float*)d_in[4];
    const float* Wk   = (const float*)d_in[5];
    const float* bk   = (const float*)d_in[6];
    const float* Wv   = (const float*)d_in[7];
    const float* bv   = (const float*)d_in[8];
    float* out = (float*)d_out;

    float *qp, *kp, *vp, *Sp;
    cudaGetSymbolAddress((void**)&qp, g_q);
    cudaGetSymbolAddress((void**)&kp, g_k);
    cudaGetSymbolAddress((void**)&vp, g_v);
    cudaGetSymbolAddress((void**)&Sp, g_S);

    dim3 blk(256);

    // Projections (scale 1/sqrt(EMB)=1/16 folded into q)
    sgemm_nt<false, true><<<dim3(2, 64), blk>>>(ego,  nullptr, Wq, bq, qp, EMB, 0.0625f);
    sgemm_nt<true,  true><<<dim3(2, 64), blk>>>(side, rel,     Wk, bk, kp, EMB, 1.0f);
    sgemm_nt<false, true><<<dim3(2, 64), blk>>>(side, nullptr, Wv, bv, vp, EMB, 1.0f);

    // Dense scores S = q' @ k^T
    sgemm_nt<false, false><<<dim3(64, 64), blk>>>(qp, nullptr, kp, nullptr, Sp, NSIDE, 1.0f);

    // Top-16 + softmax + aggregate
    topk_agg<<<dim3(NEGO / 8), blk>>>(Sp, vp, out);
}

// round 12
// speedup vs baseline: 1.3385x; 1.3385x over previous
#include <cuda_runtime.h>
#include <cuda_bf16.h>
#include <math.h>
#include <stdint.h>

#define EMB   256
#define NEGO  8192
#define NSIDE 8192
#define TOPK  16

// Scratch (device globals: allocation-free contract)
__device__ float g_q[(size_t)NEGO * EMB];
__device__ float g_k[(size_t)NSIDE * EMB];
__device__ float g_v[(size_t)NSIDE * EMB];
__device__ float g_S[(size_t)NEGO * NSIDE];
__device__ __nv_bfloat16 g_qh[(size_t)NEGO * EMB];
__device__ __nv_bfloat16 g_ql[(size_t)NEGO * EMB];
__device__ __nv_bfloat16 g_kh[(size_t)NSIDE * EMB];
__device__ __nv_bfloat16 g_kl[(size_t)NSIDE * EMB];

// ---------------------------------------------------------------------------
// Generic-PTX helpers (compute_103-safe: no tcgen05 / no 'a' features)
// ---------------------------------------------------------------------------
static __device__ __forceinline__ uint32_t smem_u32(const void* p) {
    uint32_t a;
    asm("{ .reg .u64 t; cvta.to.shared.u64 t, %1; cvt.u32.u64 %0, t; }" : "=r"(a) : "l"(p));
    return a;
}
#define SW128(o) ((o) ^ (((o) >> 3) & 0x70))

#define CP_ASYNC16(saddr, gptr) \
    asm volatile("cp.async.ca.shared.global [%0], [%1], 16;" :: "r"(saddr), "l"(gptr) : "memory")
#define CP_COMMIT()  asm volatile("cp.async.commit_group;" ::: "memory")
#define CP_WAIT(N)   asm volatile("cp.async.wait_group %0;" :: "n"(N) : "memory")

#define LDSM_X4(r0, r1, r2, r3, addr) \
    asm volatile("ldmatrix.sync.aligned.m8n8.x4.shared.b16 {%0,%1,%2,%3}, [%4];" \
                 : "=r"(r0), "=r"(r1), "=r"(r2), "=r"(r3) : "r"(addr))

#define MMA_BF16(d, a, b) \
    asm volatile("mma.sync.aligned.m16n8k16.row.col.f32.bf16.bf16.f32 " \
                 "{%0,%1,%2,%3}, {%4,%5,%6,%7}, {%8,%9}, {%0,%1,%2,%3};" \
                 : "+f"((d)[0]), "+f"((d)[1]), "+f"((d)[2]), "+f"((d)[3]) \
                 : "r"((a)[0]), "r"((a)[1]), "r"((a)[2]), "r"((a)[3]), \
                   "r"((b)[0]), "r"((b)[1]))

// ---------------------------------------------------------------------------
// fp32 SGEMM (three small projections)
// C[m][n] = (sum_d A'[m][d] * B[n][d] + bias[n]) * scale
// ---------------------------------------------------------------------------
template <bool HAS_MUL, bool HAS_BIAS>
__global__ __launch_bounds__(256, 2) void sgemm_nt(
    const float* __restrict__ A, const float* __restrict__ Amul,
    const float* __restrict__ B, const float* __restrict__ bias,
    float* __restrict__ C, int ldc, float scale)
{
    __shared__ float sA[16][132];
    __shared__ float sB[16][132];

    const int tid = threadIdx.x;
    const int tx  = tid & 15;
    const int ty  = tid >> 4;
    const int m0  = blockIdx.y * 128;
    const int n0  = blockIdx.x * 128;

    float acc[8][8];
#pragma unroll
    for (int i = 0; i < 8; i++)
#pragma unroll
        for (int j = 0; j < 8; j++) acc[i][j] = 0.f;

    for (int k0 = 0; k0 < EMB; k0 += 16) {
#pragma unroll
        for (int h = 0; h < 2; h++) {
            const int c   = tid + h * 256;
            const int r   = c >> 2;
            const int col = (c & 3) * 4;

            float4 av = *(const float4*)&A[(size_t)(m0 + r) * EMB + k0 + col];
            if (HAS_MUL) {
                float4 mv = *(const float4*)&Amul[(size_t)(m0 + r) * EMB + k0 + col];
                av.x *= mv.x; av.y *= mv.y; av.z *= mv.z; av.w *= mv.w;
            }
            sA[col + 0][r] = av.x;
            sA[col + 1][r] = av.y;
            sA[col + 2][r] = av.z;
            sA[col + 3][r] = av.w;

            float4 bv = *(const float4*)&B[(size_t)(n0 + r) * EMB + k0 + col];
            sB[col + 0][r] = bv.x;
            sB[col + 1][r] = bv.y;
            sB[col + 2][r] = bv.z;
            sB[col + 3][r] = bv.w;
        }
        __syncthreads();

#pragma unroll 2
        for (int kk = 0; kk < 16; kk++) {
            float a[8], b[8];
            *(float4*)&a[0] = *(const float4*)&sA[kk][ty * 8 + 0];
            *(float4*)&a[4] = *(const float4*)&sA[kk][ty * 8 + 4];
            *(float4*)&b[0] = *(const float4*)&sB[kk][tx * 8 + 0];
            *(float4*)&b[4] = *(const float4*)&sB[kk][tx * 8 + 4];
#pragma unroll
            for (int i = 0; i < 8; i++)
#pragma unroll
                for (int j = 0; j < 8; j++)
                    acc[i][j] = fmaf(a[i], b[j], acc[i][j]);
        }
        __syncthreads();
    }

    float bn[8];
#pragma unroll
    for (int j = 0; j < 8; j++) bn[j] = HAS_BIAS ? bias[n0 + tx * 8 + j] : 0.f;

#pragma unroll
    for (int i = 0; i < 8; i++) {
        float4 o0, o1;
        o0.x = (acc[i][0] + bn[0]) * scale;
        o0.y = (acc[i][1] + bn[1]) * scale;
        o0.z = (acc[i][2] + bn[2]) * scale;
        o0.w = (acc[i][3] + bn[3]) * scale;
        o1.x = (acc[i][4] + bn[4]) * scale;
        o1.y = (acc[i][5] + bn[5]) * scale;
        o1.z = (acc[i][6] + bn[6]) * scale;
        o1.w = (acc[i][7] + bn[7]) * scale;
        float* cp = &C[(size_t)(m0 + ty * 8 + i) * (size_t)ldc + n0 + tx * 8];
        *(float4*)(cp + 0) = o0;
        *(float4*)(cp + 4) = o1;
    }
}

// ---------------------------------------------------------------------------
// fp32 -> (bf16 hi, bf16 lo) split
// ---------------------------------------------------------------------------
__global__ __launch_bounds__(256) void cvt_split(
    const float* __restrict__ x, __nv_bfloat16* __restrict__ h, __nv_bfloat16* __restrict__ l)
{
    const int i = (blockIdx.x * 256 + threadIdx.x) * 4;
    const float4 v = *(const float4*)(x + i);
    float a[4] = {v.x, v.y, v.z, v.w};
    __nv_bfloat16 hh[4], ll[4];
#pragma unroll
    for (int j = 0; j < 4; j++) {
        hh[j] = __float2bfloat16(a[j]);
        ll[j] = __float2bfloat16(a[j] - __bfloat162float(hh[j]));
    }
    ((__nv_bfloat162*)(h + i))[0] = __nv_bfloat162(hh[0], hh[1]);
    ((__nv_bfloat162*)(h + i))[1] = __nv_bfloat162(hh[2], hh[3]);
    ((__nv_bfloat162*)(l + i))[0] = __nv_bfloat162(ll[0], ll[1]);
    ((__nv_bfloat162*)(l + i))[1] = __nv_bfloat162(ll[2], ll[3]);
}

// ---------------------------------------------------------------------------
// mma.sync bf16 split-3-pass score GEMM (generic PTX; runs on compute_103)
// S[128x128 tile] = qh*kh^T + qh*kl^T + ql*kh^T, fp32 accum.
// 8 warps as 2x4; warp tile 64x32; K chunks of 64, cp.async double-buffered
// across 12 chunks (3 passes x 4 chunks).
// ---------------------------------------------------------------------------
#define HG_BUF   32768                    // A(16KB)+B(16KB) per stage
#define HG_SMEM  (2 * HG_BUF)

__global__ __launch_bounds__(256) void hmma_gemm(
    const __nv_bfloat16* __restrict__ Ah, const __nv_bfloat16* __restrict__ Al,
    const __nv_bfloat16* __restrict__ Bh, const __nv_bfloat16* __restrict__ Bl,
    float* __restrict__ S)
{
    extern __shared__ __align__(1024) char smem[];
    const int tid  = threadIdx.x;
    const int wid  = tid >> 5;
    const int lane = tid & 31;
    const int wm   = wid >> 2;            // 0..1
    const int wn   = wid & 3;             // 0..3
    const int m0   = blockIdx.y * 128;
    const int n0   = blockIdx.x * 128;
    const uint32_t sbase = smem_u32(smem);

    const __nv_bfloat16* pA[3] = {Ah, Ah, Al};
    const __nv_bfloat16* pB[3] = {Bh, Bl, Bh};

    float d[4][4][4];
#pragma unroll
    for (int mt = 0; mt < 4; mt++)
#pragma unroll
        for (int nt = 0; nt < 4; nt++)
#pragma unroll
            for (int e = 0; e < 4; e++) d[mt][nt][e] = 0.f;

    // Issue one chunk's loads (128x64 bf16 A + B tiles, SW128-swizzled)
    auto load_chunk = [&](int idx, int buf) {
        const int pass = idx >> 2;
        const int k0   = (idx & 3) * 64;
        const __nv_bfloat16* As = pA[pass] + (size_t)m0 * EMB + k0;
        const __nv_bfloat16* Bs = pB[pass] + (size_t)n0 * EMB + k0;
        const uint32_t da = sbase + buf * HG_BUF;
        const uint32_t db = da + 16384;
#pragma unroll
        for (int h = 0; h < 4; h++) {
            const int c  = tid + h * 256;       // 16B-chunk id [0,1024)
            const int r  = c >> 3;              // row [0,128)
            const int ck = c & 7;               // 16B chunk within 128B row
            const uint32_t so = SW128((uint32_t)(r * 128 + ck * 16));
            CP_ASYNC16(da + so, (const char*)(As + (size_t)r * EMB) + ck * 16);
            CP_ASYNC16(db + so, (const char*)(Bs + (size_t)r * EMB) + ck * 16);
        }
    };

    auto compute_chunk = [&](int buf) {
        const uint32_t sa = sbase + buf * HG_BUF;
        const uint32_t sb = sa + 16384;
#pragma unroll
        for (int ks = 0; ks < 4; ks++) {
            uint32_t af[4][4], bf[4][2];
#pragma unroll
            for (int mt = 0; mt < 4; mt++) {
                const int row = wm * 64 + mt * 16 + (lane & 15);
                const uint32_t off = (uint32_t)(row * 128 + ks * 32 + ((lane >> 4) << 4));
                LDSM_X4(af[mt][0], af[mt][1], af[mt][2], af[mt][3], sa + SW128(off));
            }
#pragma unroll
            for (int p = 0; p < 2; p++) {
                const int sel = lane >> 3;      // 0..3 -> (ntile, khalf)
                const int row = wn * 32 + (p * 2 + (sel >> 1)) * 8 + (lane & 7);
                const uint32_t off = (uint32_t)(row * 128 + ks * 32 + ((sel & 1) << 4));
                LDSM_X4(bf[p * 2][0], bf[p * 2][1], bf[p * 2 + 1][0], bf[p * 2 + 1][1],
                        sb + SW128(off));
            }
#pragma unroll
            for (int mt = 0; mt < 4; mt++)
#pragma unroll
                for (int nt = 0; nt < 4; nt++)
                    MMA_BF16(d[mt][nt], af[mt], bf[nt]);
        }
    };

    load_chunk(0, 0);
    CP_COMMIT();

    for (int i = 0; i < 12; i++) {
        if (i < 11) {
            load_chunk(i + 1, (i + 1) & 1);
            CP_COMMIT();
            CP_WAIT(1);
        } else {
            CP_WAIT(0);
        }
        __syncthreads();
        compute_chunk(i & 1);
        __syncthreads();
    }

    // Epilogue: d-fragment rows t/4 (+8), cols 2(t%4)+{0,1}
#pragma unroll
    for (int mt = 0; mt < 4; mt++) {
#pragma unroll
        for (int nt = 0; nt < 4; nt++) {
            const int gr = m0 + wm * 64 + mt * 16 + (lane >> 2);
            const int gc = n0 + wn * 32 + nt * 8 + ((lane & 3) << 1);
            float2 v0 = {d[mt][nt][0], d[mt][nt][1]};
            float2 v1 = {d[mt][nt][2], d[mt][nt][3]};
            *(float2*)&S[(size_t)gr * NSIDE + gc]       = v0;
            *(float2*)&S[(size_t)(gr + 8) * NSIDE + gc] = v1;
        }
    }
}

// ---------------------------------------------------------------------------
// One warp per ego row: top-16 -> softmax -> gather/aggregate v
// 4x-unrolled scan: one ballot per 128 elements, 4 loads in flight.
// ---------------------------------------------------------------------------
__global__ __launch_bounds__(256) void topk_agg(
    const float* __restrict__ S, const float* __restrict__ V,
    float* __restrict__ out)
{
    const int warp = threadIdx.x >> 5;
    const int lane = threadIdx.x & 31;
    const int row  = blockIdx.x * 8 + warp;

    __shared__ float hv_s[8][16];
    __shared__ int   hi_s[8][16];
    float* hv = hv_s[warp];
    int*   hi = hi_s[warp];

    if (lane < 16) { hv[lane] = -INFINITY; hi[lane] = 0; }
    __syncwarp();

    float kth = -INFINITY;
    const float* Srow = S + (size_t)row * NSIDE;

    for (int j0 = 0; j0 < NSIDE; j0 += 128) {
        float s0 = Srow[j0 +  0 + lane];
        float s1 = Srow[j0 + 32 + lane];
        float s2 = Srow[j0 + 64 + lane];
        float s3 = Srow[j0 + 96 + lane];
        const float mx4 = fmaxf(fmaxf(s0, s1), fmaxf(s2, s3));
        unsigned m = __ballot_sync(0xffffffffu, mx4 > kth);
        while (m) {
            const int src = __ffs(m) - 1;
            m &= m - 1;
            float cand[4];
            cand[0] = __shfl_sync(0xffffffffu, s0, src);
            cand[1] = __shfl_sync(0xffffffffu, s1, src);
            cand[2] = __shfl_sync(0xffffffffu, s2, src);
            cand[3] = __shfl_sync(0xffffffffu, s3, src);
#pragma unroll
            for (int u = 0; u < 4; u++) {
                const float v = cand[u];
                if (v > kth) {
                    float nk = 0.f;
                    if (lane == 0) {
                        int am = 0; float mv = hv[0];
#pragma unroll
                        for (int t = 1; t < 16; t++)
                            if (hv[t] < mv) { mv = hv[t]; am = t; }
                        hv[am] = v; hi[am] = j0 + u * 32 + src;
                        mv = hv[0];
#pragma unroll
                        for (int t = 1; t < 16; t++) mv = fminf(mv, hv[t]);
                        nk = mv;
                    }
                    kth = __shfl_sync(0xffffffffu, nk, 0);
                }
            }
        }
    }
    __syncwarp();

    float topv = (lane < 16) ? hv[lane] : -INFINITY;
    float mx = topv;
#pragma unroll
    for (int o = 16; o > 0; o >>= 1) mx = fmaxf(mx, __shfl_xor_sync(0xffffffffu, mx, o));
    float e = (lane < 16) ? expf(topv - mx) : 0.f;
    float sum = e;
#pragma unroll
    for (int o = 16; o > 0; o >>= 1) sum += __shfl_xor_sync(0xffffffffu, sum, o);
    if (lane < 16) hv[lane] = e / sum;
    __syncwarp();

    float4 a0 = {0.f, 0.f, 0.f, 0.f}, a1 = {0.f, 0.f, 0.f, 0.f};
#pragma unroll
    for (int t = 0; t < 16; t++) {
        const float wt = hv[t];
        const float4* vr = (const float4*)(V + (size_t)hi[t] * EMB) + lane * 2;
        const float4 x = vr[0];
        const float4 y = vr[1];
        a0.x = fmaf(wt, x.x, a0.x); a0.y = fmaf(wt, x.y, a0.y);
        a0.z = fmaf(wt, x.z, a0.z); a0.w = fmaf(wt, x.w, a0.w);
        a1.x = fmaf(wt, y.x, a1.x); a1.y = fmaf(wt, y.y, a1.y);
        a1.z = fmaf(wt, y.z, a1.z); a1.w = fmaf(wt, y.w, a1.w);
    }
    float4* op = (float4*)(out + (size_t)row * EMB) + lane * 2;
    op[0] = a0;
    op[1] = a1;
}

// ---------------------------------------------------------------------------
extern "C" void kernel_launch(void* const* d_in, const int* in_sizes, int n_in,
                              void* d_out, int out_size)
{
    const float* ego  = (const float*)d_in[0];
    const float* side = (const float*)d_in[1];
    const float* rel  = (const float*)d_in[2];
    const float* Wq   = (const float*)d_in[3];
    const float* bq   = (const float*)d_in[4];
    const float* Wk   = (const float*)d_in[5];
    const float* bk   = (const float*)d_in[6];
    const float* Wv   = (const float*)d_in[7];
    const float* bv   = (const float*)d_in[8];
    float* out = (float*)d_out;

    float *qp, *kp, *vp, *Sp;
    __nv_bfloat16 *qh, *ql, *kh, *kl;
    cudaGetSymbolAddress((void**)&qp, g_q);
    cudaGetSymbolAddress((void**)&kp, g_k);
    cudaGetSymbolAddress((void**)&vp, g_v);
    cudaGetSymbolAddress((void**)&Sp, g_S);
    cudaGetSymbolAddress((void**)&qh, g_qh);
    cudaGetSymbolAddress((void**)&ql, g_ql);
    cudaGetSymbolAddress((void**)&kh, g_kh);
    cudaGetSymbolAddress((void**)&kl, g_kl);

    // Idempotent, capture-safe; called every time (no static guards allowed).
    cudaFuncSetAttribute(hmma_gemm, cudaFuncAttributeMaxDynamicSharedMemorySize, HG_SMEM);

    dim3 blk(256);

    // Projections (scale 1/sqrt(EMB)=1/16 folded into q)
    sgemm_nt<false, true><<<dim3(2, 64), blk>>>(ego,  nullptr, Wq, bq, qp, EMB, 0.0625f);
    sgemm_nt<true,  true><<<dim3(2, 64), blk>>>(side, rel,     Wk, bk, kp, EMB, 1.0f);
    sgemm_nt<false, true><<<dim3(2, 64), blk>>>(side, nullptr, Wv, bv, vp, EMB, 1.0f);

    // Split q,k into bf16 hi/lo
    cvt_split<<<dim3(NEGO  * EMB / 1024), blk>>>(qp, qh, ql);
    cvt_split<<<dim3(NSIDE * EMB / 1024), blk>>>(kp, kh, kl);

    // Dense scores via mma.sync bf16 (3-pass split-bf16)
    hmma_gemm<<<dim3(64, 64), blk, HG_SMEM>>>(qh, ql, kh, kl, Sp);

    // Top-16 + softmax + aggregate
    topk_agg<<<dim3(NEGO / 8), blk>>>(Sp, vp, out);
}